// round 6
// baseline (speedup 1.0000x reference)
#include <cuda_runtime.h>
#include <cuda_bf16.h>
#include <cfloat>
#include <math.h>

#define B      4096
#define INDIM  100
#define NC     4
#define NCAP   16
#define INITD  64
#define PCAP   32
#define T      16
#define L      32
#define M      33
#define D      164
#define KP     168
#define NCOL   8448
#define DIN1   64
#define DIN2   80
#define VBS    256
#define NG     16
#define EPS    1e-5f

typedef unsigned long long ull;

// ------------------------- device scratch -------------------------
__device__ float g_f[B * KP];
__device__ float g_mu[B * M];
__device__ float g_rsd[B * M];
__device__ float g_W2[KP * NCOL];
__device__ float g_S1[NCOL];
__device__ float g_S2[NCOL];
__device__ float g_priors[(size_t)B * NCOL];
__device__ float g_hsel[B * DIN1];
__device__ float g_h1[B * 96];
__device__ float g_st1[2 * NG * 96];
__device__ float g_h2[B * DIN2];
__device__ float g_g2[B * 192];
__device__ float g_st2[2 * NG * 192];
__device__ float g_mask1[3 * DIN1];
__device__ float g_mask2[3 * DIN2];

// ------------------------- f32x2 helpers -------------------------
__device__ __forceinline__ void ffma2(ull &d, ull a, ull b) {
    asm("fma.rn.f32x2 %0, %1, %2, %3;" : "=l"(d) : "l"(a), "l"(b), "l"(d));
}
__device__ __forceinline__ ull pack2(float x, float y) {
    ull r; asm("mov.b64 %0, {%1, %2};" : "=l"(r) : "f"(x), "f"(y)); return r;
}
__device__ __forceinline__ float2 unpack2(ull v) {
    float2 r; asm("mov.b64 {%0, %1}, %2;" : "=f"(r.x), "=f"(r.y) : "l"(v)); return r;
}

// ---------------- K1: f = [x, x@Wi^T+bi]; per-(b,m) mu/rsd --------
__global__ void k_prep(const float* __restrict__ x, const float* __restrict__ iw,
                       const float* __restrict__ ib, const float* __restrict__ pfc) {
    __shared__ float fsh[KP];
    int b = blockIdx.x, tid = threadIdx.x;
    if (tid < INDIM) fsh[tid] = x[b * INDIM + tid];
    __syncthreads();
    if (tid >= INDIM && tid < D) {
        int j = tid - INDIM;
        float a = ib[j];
        const float* wr = iw + j * INDIM;
        #pragma unroll 4
        for (int k = 0; k < INDIM; k++) a += wr[k] * fsh[k];
        fsh[tid] = a;
    }
    if (tid >= D && tid < KP) fsh[tid] = 0.f;
    __syncthreads();
    if (tid < KP) g_f[b * KP + tid] = fsh[tid];
    if (tid < M) {
        float s1 = 0.f, s2 = 0.f;
        for (int d = 0; d < D; d++) {
            float p = (tid < PCAP) ? pfc[d * PCAP + tid] : 1.f;
            float v = fsh[d] * p;
            s1 += v; s2 += v * v;
        }
        float mu = s1 * (1.f / (float)D);
        float var = s2 * (1.f / (float)D) - mu * mu;
        g_mu[b * M + tid] = mu;
        g_rsd[b * M + tid] = rsqrtf(var + EPS);
    }
}

// ---------------- entmax15 block primitive ------------------------
template <int NP>
__device__ __forceinline__ float entmax_tau_block(float* xo, float* srt, float* cs,
                                                  float* cs2, float* tau, float* red,
                                                  int d) {
    int tid = threadIdx.x;
    red[tid] = xo[tid];
    __syncthreads();
    for (int s = NP / 2; s > 0; s >>= 1) {
        if (tid < s) red[tid] = fmaxf(red[tid], red[tid + s]);
        __syncthreads();
    }
    float mx = red[0];
    __syncthreads();
    float xv = (tid < d) ? (xo[tid] - mx) * 0.5f : -FLT_MAX;
    xo[tid] = xv;
    srt[tid] = xv;
    __syncthreads();
    for (int k = 2; k <= NP; k <<= 1) {
        for (int j = k >> 1; j > 0; j >>= 1) {
            int ixj = tid ^ j;
            if (ixj > tid) {
                float a = srt[tid], b2 = srt[ixj];
                bool up = ((tid & k) == 0);
                bool sw = up ? (a < b2) : (a > b2);
                if (sw) { srt[tid] = b2; srt[ixj] = a; }
            }
            __syncthreads();
        }
    }
    float sv = srt[tid];
    cs[tid] = sv; cs2[tid] = sv * sv;
    __syncthreads();
    for (int off = 1; off < NP; off <<= 1) {
        float a = 0.f, a2 = 0.f;
        if (tid >= off) { a = cs[tid - off]; a2 = cs2[tid - off]; }
        __syncthreads();
        cs[tid] += a; cs2[tid] += a2;
        __syncthreads();
    }
    if (tid < d) {
        float rho = (float)(tid + 1);
        float mean = cs[tid] / rho;
        float msq = cs2[tid] / rho;
        float ss = rho * (msq - mean * mean);
        float delta = fmaxf((1.f - ss) / rho, 0.f);
        tau[tid] = mean - sqrtf(delta);
    }
    __syncthreads();
    red[tid] = (tid < d && tau[tid] <= sv) ? 1.f : 0.f;
    __syncthreads();
    for (int s = NP / 2; s > 0; s >>= 1) {
        if (tid < s) red[tid] += red[tid + s];
        __syncthreads();
    }
    int sup = (int)red[0];
    __syncthreads();
    return tau[sup - 1];
}

// ---------------- K2: entmax(route_w) + fold into W2/S1/S2 --------
__global__ void k_entmax_route(const float* __restrict__ rw, const float* __restrict__ g,
                               const float* __restrict__ beta, const float* __restrict__ pfc) {
    __shared__ float xo[256], srt[256], cs[256], cs2[256], tau[256], red[256];
    int col = blockIdx.x;
    int m = col >> 8, nn = (col >> 4) & 15, t = col & 15;
    int tid = threadIdx.x;
    xo[tid] = (tid < D) ? rw[((size_t)(m * NCAP + nn) * D + tid) * T + t] : -FLT_MAX;
    __syncthreads();
    float ts = entmax_tau_block<256>(xo, srt, cs, cs2, tau, red, D);
    float w = 0.f;
    if (tid < D) {
        float r = fmaxf(xo[tid] - ts, 0.f);
        w = r * r;
        float pm = (m < PCAP) ? pfc[tid * PCAP + m] : 1.f;
        g_W2[tid * NCOL + col] = w * pm * g[tid];
    } else if (tid < KP) {
        g_W2[tid * NCOL + col] = 0.f;
    }
    __syncthreads();
    red[tid] = (tid < D) ? w * g[tid] : 0.f;
    cs[tid]  = (tid < D) ? w * beta[tid] : 0.f;
    __syncthreads();
    for (int s = 128; s > 0; s >>= 1) {
        if (tid < s) { red[tid] += red[tid + s]; cs[tid] += cs[tid + s]; }
        __syncthreads();
    }
    if (tid == 0) { g_S1[col] = red[0]; g_S2[col] = cs[0]; }
}

// ---------------- K3: GEMM 128x64 tiles, dup-B, f32x2 FMA ---------
__global__ __launch_bounds__(256, 3) void k_gemm() {
    __shared__ __align__(16) float As[8][128];
    __shared__ __align__(16) float Bs[8][128];   // duplicated pairs (v,v)
    int tid = threadIdx.x;
    int bn0 = blockIdx.x * 64, bm0 = blockIdx.y * 128;
    int am = tid >> 1, ak = (tid & 1) * 4;
    int bk = tid >> 4, bc = (tid & 15) * 4;
    bool bload = tid < 128;
    const float* Ap = g_f + (bm0 + am) * KP + ak;
    const float* Bp = g_W2 + bk * NCOL + bn0 + bc;
    float4 ra = *(const float4*)Ap;
    float4 rb = bload ? *(const float4*)Bp : make_float4(0, 0, 0, 0);
    ull acc[4][4];
    #pragma unroll
    for (int i = 0; i < 4; i++)
        #pragma unroll
        for (int j = 0; j < 4; j++) acc[i][j] = 0ULL;
    int ty = tid >> 4, tx = tid & 15;
    for (int k0 = 0; k0 < KP; k0 += 8) {
        As[ak + 0][am] = ra.x; As[ak + 1][am] = ra.y;
        As[ak + 2][am] = ra.z; As[ak + 3][am] = ra.w;
        if (bload) {
            ull* d64 = (ull*)&Bs[bk][2 * bc];
            d64[0] = pack2(rb.x, rb.x); d64[1] = pack2(rb.y, rb.y);
            d64[2] = pack2(rb.z, rb.z); d64[3] = pack2(rb.w, rb.w);
        }
        __syncthreads();
        if (k0 + 8 < KP) {
            ra = *(const float4*)(Ap + (k0 + 8));
            if (bload) rb = *(const float4*)(Bp + (size_t)(k0 + 8) * NCOL);
        }
        #pragma unroll
        for (int kk = 0; kk < 8; kk++) {
            const ulonglong2* ap2 = (const ulonglong2*)&As[kk][ty * 8];
            ulonglong2 av0 = ap2[0], av1 = ap2[1];
            const ull* bp = (const ull*)&Bs[kk][tx * 8];
            ull b0 = bp[0], b1 = bp[1], b2 = bp[2], b3 = bp[3];
            ffma2(acc[0][0], av0.x, b0); ffma2(acc[0][1], av0.x, b1);
            ffma2(acc[0][2], av0.x, b2); ffma2(acc[0][3], av0.x, b3);
            ffma2(acc[1][0], av0.y, b0); ffma2(acc[1][1], av0.y, b1);
            ffma2(acc[1][2], av0.y, b2); ffma2(acc[1][3], av0.y, b3);
            ffma2(acc[2][0], av1.x, b0); ffma2(acc[2][1], av1.x, b1);
            ffma2(acc[2][2], av1.x, b2); ffma2(acc[2][3], av1.x, b3);
            ffma2(acc[3][0], av1.y, b0); ffma2(acc[3][1], av1.y, b1);
            ffma2(acc[3][2], av1.y, b2); ffma2(acc[3][3], av1.y, b3);
        }
        __syncthreads();
    }
    // epilogue: priors = (C - mu*S1)*rsd + S2
    int c0 = bn0 + tx * 4;
    int mi = c0 >> 8;
    float s1[4], s2[4];
    #pragma unroll
    for (int j = 0; j < 4; j++) { s1[j] = g_S1[c0 + j]; s2[j] = g_S2[c0 + j]; }
    #pragma unroll
    for (int ii = 0; ii < 4; ii++) {
        int r0 = bm0 + ty * 8 + 2 * ii;
        float mu0 = g_mu[r0 * M + mi], rs0 = g_rsd[r0 * M + mi];
        float mu1 = g_mu[(r0 + 1) * M + mi], rs1 = g_rsd[(r0 + 1) * M + mi];
        float* o0 = g_priors + (size_t)r0 * NCOL + c0;
        float* o1 = o0 + NCOL;
        #pragma unroll
        for (int j = 0; j < 4; j++) {
            float2 v = unpack2(acc[ii][j]);
            o0[j] = (v.x - mu0 * s1[j]) * rs0 + s2[j];
            o1[j] = (v.y - mu1 * s1[j]) * rs1 + s2[j];
        }
    }
}

// ---------------- K4: fused routing, warp-per-capsule -------------
__global__ __launch_bounds__(256) void k_route(const float* __restrict__ leaves,
                                               const float* __restrict__ thr,
                                               const float* __restrict__ cg,
                                               const float* __restrict__ cb,
                                               const float* __restrict__ y,
                                               float* __restrict__ outp) {
    __shared__ __align__(16) float pri[NCOL];     // 33.8 KB
    __shared__ float thrsh[M * NCAP];
    __shared__ float probw[8][34];
    __shared__ float hid[NCAP * T];
    __shared__ float snorm[NCAP];
    __shared__ float ysh[NC];
    __shared__ float cgs[T], cbs[T];
    int b = blockIdx.x, tid = threadIdx.x;
    int lane = tid & 31, w = tid >> 5;
    const float4* src = (const float4*)(g_priors + (size_t)b * NCOL);
    for (int i = tid; i < NCOL / 4; i += 256) ((float4*)pri)[i] = src[i];
    for (int i = tid; i < M * NCAP; i += 256) thrsh[i] = thr[i];
    if (tid < NC) ysh[tid] = y[b * NC + tid];
    if (tid < T) { cgs[tid] = cg[tid]; cbs[tid] = cb[tid]; }
    // normalized leaf for this lane, cached in registers
    float lf[T];
    float ss = 0.f;
    #pragma unroll
    for (int t = 0; t < T; t++) { lf[t] = leaves[lane * T + t]; ss += lf[t] * lf[t]; }
    float invn = 1.f / fmaxf(sqrtf(ss), 1e-12f);
    ull lh8[8];
    #pragma unroll
    for (int i = 0; i < 8; i++) lh8[i] = pack2(lf[2 * i] * invn, lf[2 * i + 1] * invn);
    __syncthreads();

    #pragma unroll
    for (int rep = 0; rep < 2; rep++) {
        int n = w * 2 + rep;
        // votes: v[m] = sigmoid(dot(pri[m,n,:], lh[lane,:]))
        float v[M];
        #pragma unroll
        for (int m = 0; m < M; m++) {
            const ull* pp = (const ull*)&pri[m * 256 + n * T];   // warp broadcast
            ull a = 0ULL;
            #pragma unroll
            for (int i = 0; i < 8; i++) ffma2(a, pp[i], lh8[i]);
            float2 s2v = unpack2(a);
            float d = s2v.x + s2v.y;
            v[m] = 1.f / (1.f + __expf(-d));
        }
        // vbar over m (per-lane leaf)
        float vb = 0.f;
        #pragma unroll
        for (int m = 0; m < M; m++) vb += v[m];
        vb *= (1.f / 33.f);
        // dis per m via butterfly over leaves; keep lane's wgt + wgt[32]
        float wgt_own = 0.f, wgt32 = 0.f;
        #pragma unroll
        for (int m = 0; m < M; m++) {
            float d = v[m] - vb;
            d *= d;
            #pragma unroll
            for (int o = 16; o; o >>= 1) d += __shfl_xor_sync(0xffffffffu, d, o);
            float dis = d * (1.f / 32.f);
            float th = thrsh[m * NCAP + n];
            float wv = th * th - dis;
            wv = wv > 0.f ? wv : 0.f;
            if (m == lane) wgt_own = wv;
            if (m == 32) wgt32 = wv;
        }
        // softmax over 33 (32 lanes + the m=32 value everyone holds)
        float mx = fmaxf(wgt_own, wgt32);
        #pragma unroll
        for (int o = 16; o; o >>= 1) mx = fmaxf(mx, __shfl_xor_sync(0xffffffffu, mx, o));
        float e = __expf(wgt_own - mx);
        float e32 = __expf(wgt32 - mx);
        float sm = e;
        #pragma unroll
        for (int o = 16; o; o >>= 1) sm += __shfl_xor_sync(0xffffffffu, sm, o);
        float inv = 1.f / (sm + e32);
        probw[w][lane] = e * inv;
        if (lane == 0) probw[w][32] = e32 * inv;
        __syncwarp();
        // hidden + LN (lanes 0..15, lane = t)
        if (lane < T) {
            float h = 0.f;
            #pragma unroll
            for (int m = 0; m < M; m++) h += probw[w][m] * pri[m * 256 + n * T + lane];
            float s = h;
            #pragma unroll
            for (int o = 8; o; o >>= 1) s += __shfl_xor_sync(0xffffu, s, o);
            float mean = s * (1.f / 16.f);
            float dv = h - mean;
            float vs = dv * dv;
            #pragma unroll
            for (int o = 8; o; o >>= 1) vs += __shfl_xor_sync(0xffffu, vs, o);
            float rs = rsqrtf(vs * (1.f / 16.f) + EPS);
            float hl = dv * rs * cgs[lane] + cbs[lane];
            hid[n * T + lane] = hl;
            float q = hl * hl;
            #pragma unroll
            for (int o = 8; o; o >>= 1) q += __shfl_xor_sync(0xffffu, q, o);
            if (lane == 0) snorm[n] = sqrtf(q);
        }
        __syncwarp();
    }
    __syncthreads();
    if (tid < NC) {
        float s = snorm[tid * 4 + 0] + snorm[tid * 4 + 1] +
                  snorm[tid * 4 + 2] + snorm[tid * 4 + 3];
        outp[b * NC + tid] = s;
    }
    if (tid < DIN1) {
        int s = tid >> 4, t = tid & 15;
        float a = 0.f;
        #pragma unroll
        for (int c = 0; c < NC; c++) a += hid[(s * 4 + c) * T + t] * ysh[c];
        g_hsel[b * DIN1 + tid] = a;
    }
}

// ---------------- K5: entmax of decoder masks ---------------------
__global__ void k_entmax_small(const float* __restrict__ m1, const float* __restrict__ m2) {
    __shared__ float xo[128], srt[128], cs[128], cs2[128], tau[128], red[128];
    int bi = blockIdx.x, tid = threadIdx.x;
    int which = bi / 3, p = bi % 3;
    int d = which ? DIN2 : DIN1;
    const float* s = which ? (m2 + p * DIN2) : (m1 + p * DIN1);
    float* dst = which ? (g_mask2 + p * DIN2) : (g_mask1 + p * DIN1);
    xo[tid] = (tid < d) ? s[tid] : -FLT_MAX;
    __syncthreads();
    float ts = entmax_tau_block<128>(xo, srt, cs, cs2, tau, red, d);
    if (tid < d) {
        float r = fmaxf(xo[tid] - ts, 0.f);
        dst[tid] = r * r;
    }
}

// ---------------- K7: h1 = hsel @ (mask1*W1)^T + b1 ---------------
__global__ void k_h1(const float* __restrict__ b1, const float* __restrict__ w1) {
    __shared__ float xs[DIN1];
    __shared__ float msk[3 * DIN1];
    int b = blockIdx.x, tid = threadIdx.x;   // 96 threads
    if (tid < DIN1) xs[tid] = g_hsel[b * DIN1 + tid];
    for (int i = tid; i < 3 * DIN1; i += 96) msk[i] = g_mask1[i];
    __syncthreads();
    float a = b1[tid];
    const float* wr = w1 + tid * DIN1;
    const float* mr = msk + (tid >> 5) * DIN1;
    #pragma unroll 4
    for (int d = 0; d < DIN1; d++) a += wr[d] * mr[d] * xs[d];
    g_h1[b * 96 + tid] = a;
}

// ---------------- GhostBN stats (device-side global refs) ---------
__global__ void k_gbn_stats1() {
    int g = blockIdx.x, j = threadIdx.x;          // F = 96
    const float* p = g_h1 + (size_t)g * VBS * 96 + j;
    float s = 0.f, s2 = 0.f;
    for (int r = 0; r < VBS; r++) {
        float v = p[r * 96];
        s += v; s2 += v * v;
    }
    float mean = s * (1.f / (float)VBS);
    float var = s2 * (1.f / (float)VBS) - mean * mean;
    g_st1[g * 96 + j] = mean;
    g_st1[NG * 96 + g * 96 + j] = rsqrtf(var + EPS);
}

__global__ void k_gbn_stats2() {
    int g = blockIdx.x, j = threadIdx.x;          // F = 192
    const float* p = g_g2 + (size_t)g * VBS * 192 + j;
    float s = 0.f, s2 = 0.f;
    for (int r = 0; r < VBS; r++) {
        float v = p[r * 192];
        s += v; s2 += v * v;
    }
    float mean = s * (1.f / (float)VBS);
    float var = s2 * (1.f / (float)VBS) - mean * mean;
    g_st2[g * 192 + j] = mean;
    g_st2[NG * 192 + g * 192 + j] = rsqrtf(var + EPS);
}

// ---------------- K9: apply GBN1 + GLU + build h2 -----------------
__global__ void k_apply1(const float* __restrict__ bg, const float* __restrict__ bb) {
    __shared__ float hh[96];
    int b = blockIdx.x, tid = threadIdx.x;
    int g = b >> 8;
    float v = g_h1[b * 96 + tid];
    float mean = g_st1[g * 96 + tid];
    float rs = g_st1[NG * 96 + g * 96 + tid];
    hh[tid] = (v - mean) * rs * bg[tid] + bb[tid];
    __syncthreads();
    if (tid < 16) {
        float s = 0.f;
        #pragma unroll
        for (int p = 0; p < 3; p++) {
            float gte = 1.f / (1.f + __expf(-hh[p * 32 + tid]));
            float pr = gte * hh[p * 32 + 16 + tid];
            s += pr > 0.f ? pr : 0.f;
        }
        g_h2[b * DIN2 + DIN1 + tid] = s;
    }
    if (tid < DIN1) g_h2[b * DIN2 + tid] = g_hsel[b * DIN1 + tid];
}

// ---------------- K10: g2 = h2 @ (mask2*W2)^T + b2 ----------------
__global__ void k_h2(const float* __restrict__ b2, const float* __restrict__ w2) {
    __shared__ float xs[DIN2];
    __shared__ float msk[3 * DIN2];
    int b = blockIdx.x, tid = threadIdx.x;   // 192 threads
    if (tid < DIN2) xs[tid] = g_h2[b * DIN2 + tid];
    for (int i = tid; i < 3 * DIN2; i += 192) msk[i] = g_mask2[i];
    __syncthreads();
    float a = b2[tid];
    const float* wr = w2 + tid * DIN2;
    const float* mr = msk + (tid / 64) * DIN2;
    #pragma unroll 4
    for (int d = 0; d < DIN2; d++) a += wr[d] * mr[d] * xs[d];
    g_g2[b * 192 + tid] = a;
}

// ---------------- K12: apply GBN2 + GLU + final linear ------------
__global__ void k_apply2(const float* __restrict__ bg, const float* __restrict__ bb,
                         const float* __restrict__ dw, const float* __restrict__ db,
                         float* __restrict__ rec) {
    __shared__ float hh[192];
    __shared__ float o2[32];
    int b = blockIdx.x, tid = threadIdx.x;
    int g = b >> 8;
    float v = g_g2[b * 192 + tid];
    float mean = g_st2[g * 192 + tid];
    float rs = g_st2[NG * 192 + g * 192 + tid];
    hh[tid] = (v - mean) * rs * bg[tid] + bb[tid];
    __syncthreads();
    if (tid < 32) {
        float s = 0.f;
        #pragma unroll
        for (int p = 0; p < 3; p++) {
            float gte = 1.f / (1.f + __expf(-hh[p * 64 + tid]));
            float pr = gte * hh[p * 64 + 32 + tid];
            s += pr > 0.f ? pr : 0.f;
        }
        o2[tid] = s;
    }
    __syncthreads();
    if (tid < INDIM) {
        float a = db[tid];
        const float* wr = dw + tid * 32;
        #pragma unroll
        for (int o = 0; o < 32; o++) a += wr[o] * o2[o];
        rec[b * INDIM + tid] = a;
    }
}

// ------------------------- launch ---------------------------------
extern "C" void kernel_launch(void* const* d_in, const int* in_sizes, int n_in,
                              void* d_out, int out_size) {
    const float* x       = (const float*)d_in[0];
    const float* y       = (const float*)d_in[1];
    const float* init_w  = (const float*)d_in[2];
    const float* init_b  = (const float*)d_in[3];
    const float* eln_g   = (const float*)d_in[4];
    const float* eln_b   = (const float*)d_in[5];
    const float* prim_fc = (const float*)d_in[6];
    const float* route_w = (const float*)d_in[7];
    const float* thread_ = (const float*)d_in[8];
    const float* leaves  = (const float*)d_in[9];
    const float* cln_g   = (const float*)d_in[10];
    const float* cln_b   = (const float*)d_in[11];
    const float* m1_w    = (const float*)d_in[12];
    const float* fc1_w   = (const float*)d_in[13];
    const float* fc1_b   = (const float*)d_in[14];
    const float* bn1_g   = (const float*)d_in[15];
    const float* bn1_b   = (const float*)d_in[16];
    const float* m2_w    = (const float*)d_in[17];
    const float* fc2_w   = (const float*)d_in[18];
    const float* fc2_b   = (const float*)d_in[19];
    const float* bn2_g   = (const float*)d_in[20];
    const float* bn2_b   = (const float*)d_in[21];
    const float* dec_w   = (const float*)d_in[22];
    const float* dec_b   = (const float*)d_in[23];
    float* out = (float*)d_out;           // [B*NC pred][B*INDIM rec]

    k_prep<<<B, 192>>>(x, init_w, init_b, prim_fc);
    k_entmax_route<<<NCOL, 256>>>(route_w, eln_g, eln_b, prim_fc);
    k_entmax_small<<<6, 128>>>(m1_w, m2_w);
    k_gemm<<<dim3(NCOL / 64, B / 128), 256>>>();
    k_route<<<B, 256>>>(leaves, thread_, cln_g, cln_b, y, out);
    k_h1<<<B, 96>>>(fc1_b, fc1_w);
    k_gbn_stats1<<<NG, 96>>>();
    k_apply1<<<B, 96>>>(bn1_g, bn1_b);
    k_h2<<<B, 192>>>(fc2_b, fc2_w);
    k_gbn_stats2<<<NG, 192>>>();
    k_apply2<<<B, 192>>>(bn2_g, bn2_b, dec_w, dec_b, out + B * NC);
}

// round 17
// speedup vs baseline: 1.3076x; 1.3076x over previous
#include <cuda_runtime.h>
#include <cuda_bf16.h>
#include <cfloat>
#include <math.h>

#define B      4096
#define INDIM  100
#define NC     4
#define NCAP   16
#define INITD  64
#define PCAP   32
#define T      16
#define L      32
#define M      33
#define D      164
#define KP     168
#define NCOL   8448
#define DIN1   64
#define DIN2   80
#define VBS    256
#define NG     16
#define EPS    1e-5f
#define KB     24

typedef unsigned long long ull;

// ------------------------- device scratch -------------------------
__device__ float g_f[B * KP];
__device__ float g_mu[B * M];
__device__ float g_rsd[B * M];
__device__ float g_W2[KP * NCOL];
__device__ float g_S1[NCOL];
__device__ float g_S2[NCOL];
__device__ float g_priors[(size_t)B * NCOL];
__device__ float g_hsel[B * DIN1];
__device__ float g_h1[B * 96];
__device__ float g_st1[2 * NG * 96];
__device__ float g_h2[B * DIN2];
__device__ float g_g2[B * 192];
__device__ float g_st2[2 * NG * 192];
__device__ float g_mask1[3 * DIN1];
__device__ float g_mask2[3 * DIN2];

// ------------------------- f32x2 helpers -------------------------
__device__ __forceinline__ void ffma2(ull &d, ull a, ull b) {
    asm("fma.rn.f32x2 %0, %1, %2, %3;" : "=l"(d) : "l"(a), "l"(b), "l"(d));
}
__device__ __forceinline__ ull pack2(float x, float y) {
    ull r; asm("mov.b64 %0, {%1, %2};" : "=l"(r) : "f"(x), "f"(y)); return r;
}
__device__ __forceinline__ float2 unpack2(ull v) {
    float2 r; asm("mov.b64 {%0, %1}, %2;" : "=f"(r.x), "=f"(r.y) : "l"(v)); return r;
}

// ---------------- K1: f = [x, x@Wi^T+bi]; per-(b,m) mu/rsd --------
__global__ void k_prep(const float* __restrict__ x, const float* __restrict__ iw,
                       const float* __restrict__ ib, const float* __restrict__ pfc) {
    __shared__ float fsh[KP];
    int b = blockIdx.x, tid = threadIdx.x;
    if (tid < INDIM) fsh[tid] = x[b * INDIM + tid];
    __syncthreads();
    if (tid >= INDIM && tid < D) {
        int j = tid - INDIM;
        float a = ib[j];
        const float* wr = iw + j * INDIM;
        #pragma unroll 4
        for (int k = 0; k < INDIM; k++) a += wr[k] * fsh[k];
        fsh[tid] = a;
    }
    if (tid >= D && tid < KP) fsh[tid] = 0.f;
    __syncthreads();
    if (tid < KP) g_f[b * KP + tid] = fsh[tid];
    if (tid < M) {
        float s1 = 0.f, s2 = 0.f;
        for (int d = 0; d < D; d++) {
            float p = (tid < PCAP) ? pfc[d * PCAP + tid] : 1.f;
            float v = fsh[d] * p;
            s1 += v; s2 += v * v;
        }
        float mu = s1 * (1.f / (float)D);
        float var = s2 * (1.f / (float)D) - mu * mu;
        g_mu[b * M + tid] = mu;
        g_rsd[b * M + tid] = rsqrtf(var + EPS);
    }
}

// ---------------- entmax15 block primitive ------------------------
template <int NP>
__device__ __forceinline__ float entmax_tau_block(float* xo, float* srt, float* cs,
                                                  float* cs2, float* tau, float* red,
                                                  int d) {
    int tid = threadIdx.x;
    red[tid] = xo[tid];
    __syncthreads();
    for (int s = NP / 2; s > 0; s >>= 1) {
        if (tid < s) red[tid] = fmaxf(red[tid], red[tid + s]);
        __syncthreads();
    }
    float mx = red[0];
    __syncthreads();
    float xv = (tid < d) ? (xo[tid] - mx) * 0.5f : -FLT_MAX;
    xo[tid] = xv;
    srt[tid] = xv;
    __syncthreads();
    for (int k = 2; k <= NP; k <<= 1) {
        for (int j = k >> 1; j > 0; j >>= 1) {
            int ixj = tid ^ j;
            if (ixj > tid) {
                float a = srt[tid], b2 = srt[ixj];
                bool up = ((tid & k) == 0);
                bool sw = up ? (a < b2) : (a > b2);
                if (sw) { srt[tid] = b2; srt[ixj] = a; }
            }
            __syncthreads();
        }
    }
    float sv = srt[tid];
    cs[tid] = sv; cs2[tid] = sv * sv;
    __syncthreads();
    for (int off = 1; off < NP; off <<= 1) {
        float a = 0.f, a2 = 0.f;
        if (tid >= off) { a = cs[tid - off]; a2 = cs2[tid - off]; }
        __syncthreads();
        cs[tid] += a; cs2[tid] += a2;
        __syncthreads();
    }
    if (tid < d) {
        float rho = (float)(tid + 1);
        float mean = cs[tid] / rho;
        float msq = cs2[tid] / rho;
        float ss = rho * (msq - mean * mean);
        float delta = fmaxf((1.f - ss) / rho, 0.f);
        tau[tid] = mean - sqrtf(delta);
    }
    __syncthreads();
    red[tid] = (tid < d && tau[tid] <= sv) ? 1.f : 0.f;
    __syncthreads();
    for (int s = NP / 2; s > 0; s >>= 1) {
        if (tid < s) red[tid] += red[tid + s];
        __syncthreads();
    }
    int sup = (int)red[0];
    __syncthreads();
    return tau[sup - 1];
}

// ---------------- K2: entmax(route_w) + fold into W2/S1/S2 --------
__global__ void k_entmax_route(const float* __restrict__ rw, const float* __restrict__ g,
                               const float* __restrict__ beta, const float* __restrict__ pfc) {
    __shared__ float xo[256], srt[256], cs[256], cs2[256], tau[256], red[256];
    int col = blockIdx.x;
    int m = col >> 8, nn = (col >> 4) & 15, t = col & 15;
    int tid = threadIdx.x;
    xo[tid] = (tid < D) ? rw[((size_t)(m * NCAP + nn) * D + tid) * T + t] : -FLT_MAX;
    __syncthreads();
    float ts = entmax_tau_block<256>(xo, srt, cs, cs2, tau, red, D);
    float w = 0.f;
    if (tid < D) {
        float r = fmaxf(xo[tid] - ts, 0.f);
        w = r * r;
        float pm = (m < PCAP) ? pfc[tid * PCAP + m] : 1.f;
        g_W2[tid * NCOL + col] = w * pm * g[tid];
    } else if (tid < KP) {
        g_W2[tid * NCOL + col] = 0.f;
    }
    __syncthreads();
    red[tid] = (tid < D) ? w * g[tid] : 0.f;
    cs[tid]  = (tid < D) ? w * beta[tid] : 0.f;
    __syncthreads();
    for (int s = 128; s > 0; s >>= 1) {
        if (tid < s) { red[tid] += red[tid + s]; cs[tid] += cs[tid + s]; }
        __syncthreads();
    }
    if (tid == 0) { g_S1[col] = red[0]; g_S2[col] = cs[0]; }
}

// ---------------- K3: GEMM 128x128 tiles, 8x8/thread, f32x2 -------
// A pairs over M (k-major smem). B plain k-major, quad-swizzled
// (phys_quad = q ^ ((q>>3)&1)) so all LDS.128 are conflict-free.
__global__ __launch_bounds__(256, 2) void k_gemm() {
    __shared__ __align__(16) float As[KB][128];
    __shared__ __align__(16) float Bs[KB][128];
    int tid = threadIdx.x;
    int bn0 = blockIdx.x * 128, bm0 = blockIdx.y * 128;
    int lane = tid & 31, w = tid >> 5;
    int wm = w & 3, wn = w >> 2;         // 4 warps along M, 2 along N
    int my = lane >> 3, nx = lane & 7;
    int rowb = wm * 32 + my * 8;         // 8 M-rows per thread
    int q0 = wn * 16 + 2 * nx;           // base logical B quad (8 N-cols)
    int bxor = (nx >> 2) & 1;            // swizzle bit for this thread's quads
    int colb = wn * 64 + nx * 8;

    // loader indices
    int ar = tid & 127;                  // A row (conflict-free STS.32 banks)
    int ah = tid >> 7;                   // A kc4 parity
    int bq = tid & 31;                   // B quad within row
    int bkr = tid >> 5;                  // B k-row base
    int bqp = bq ^ ((bq >> 3) & 1);      // phys quad for B store

    const float* Ap = g_f + (bm0 + ar) * KP;
    const float* Bp = g_W2 + bn0 + bq * 4;

    float4 ra[3], rb[3];
    #pragma unroll
    for (int i = 0; i < 3; i++) {
        ra[i] = *(const float4*)(Ap + (ah + 2 * i) * 4);
        rb[i] = *(const float4*)(Bp + (size_t)(bkr + 8 * i) * NCOL);
    }

    ull acc[4][8];
    #pragma unroll
    for (int p = 0; p < 4; p++)
        #pragma unroll
        for (int j = 0; j < 8; j++) acc[p][j] = 0ULL;

    int k0 = 0;
    while (true) {
        #pragma unroll
        for (int i = 0; i < 3; i++) {
            int kc4 = (ah + 2 * i) * 4;
            As[kc4 + 0][ar] = ra[i].x; As[kc4 + 1][ar] = ra[i].y;
            As[kc4 + 2][ar] = ra[i].z; As[kc4 + 3][ar] = ra[i].w;
            *(float4*)&Bs[bkr + 8 * i][bqp * 4] = rb[i];
        }
        __syncthreads();
        int kn = k0 + KB;
        if (kn < KP) {
            #pragma unroll
            for (int i = 0; i < 3; i++) {
                ra[i] = *(const float4*)(Ap + kn + (ah + 2 * i) * 4);
                rb[i] = *(const float4*)(Bp + (size_t)(kn + bkr + 8 * i) * NCOL);
            }
        }
        #pragma unroll
        for (int kk = 0; kk < KB; kk++) {
            ulonglong2 aA = *(const ulonglong2*)&As[kk][rowb];
            ulonglong2 aB = *(const ulonglong2*)&As[kk][rowb + 4];
            float4 b0 = *(const float4*)&Bs[kk][(q0 ^ bxor) * 4];
            float4 b1 = *(const float4*)&Bs[kk][((q0 + 1) ^ bxor) * 4];
            ull bd0 = pack2(b0.x, b0.x), bd1 = pack2(b0.y, b0.y);
            ull bd2 = pack2(b0.z, b0.z), bd3 = pack2(b0.w, b0.w);
            ull bd4 = pack2(b1.x, b1.x), bd5 = pack2(b1.y, b1.y);
            ull bd6 = pack2(b1.z, b1.z), bd7 = pack2(b1.w, b1.w);
            ffma2(acc[0][0], aA.x, bd0); ffma2(acc[0][1], aA.x, bd1);
            ffma2(acc[0][2], aA.x, bd2); ffma2(acc[0][3], aA.x, bd3);
            ffma2(acc[0][4], aA.x, bd4); ffma2(acc[0][5], aA.x, bd5);
            ffma2(acc[0][6], aA.x, bd6); ffma2(acc[0][7], aA.x, bd7);
            ffma2(acc[1][0], aA.y, bd0); ffma2(acc[1][1], aA.y, bd1);
            ffma2(acc[1][2], aA.y, bd2); ffma2(acc[1][3], aA.y, bd3);
            ffma2(acc[1][4], aA.y, bd4); ffma2(acc[1][5], aA.y, bd5);
            ffma2(acc[1][6], aA.y, bd6); ffma2(acc[1][7], aA.y, bd7);
            ffma2(acc[2][0], aB.x, bd0); ffma2(acc[2][1], aB.x, bd1);
            ffma2(acc[2][2], aB.x, bd2); ffma2(acc[2][3], aB.x, bd3);
            ffma2(acc[2][4], aB.x, bd4); ffma2(acc[2][5], aB.x, bd5);
            ffma2(acc[2][6], aB.x, bd6); ffma2(acc[2][7], aB.x, bd7);
            ffma2(acc[3][0], aB.y, bd0); ffma2(acc[3][1], aB.y, bd1);
            ffma2(acc[3][2], aB.y, bd2); ffma2(acc[3][3], aB.y, bd3);
            ffma2(acc[3][4], aB.y, bd4); ffma2(acc[3][5], aB.y, bd5);
            ffma2(acc[3][6], aB.y, bd6); ffma2(acc[3][7], aB.y, bd7);
        }
        __syncthreads();
        if (kn >= KP) break;
        k0 = kn;
    }

    // epilogue: priors = (C - mu*S1)*rsd + S2
    int c0 = bn0 + colb;
    int mi = c0 >> 8;        // 8 cols never cross a 256-col m-block
    float4 s1a = *(const float4*)(g_S1 + c0);
    float4 s1b = *(const float4*)(g_S1 + c0 + 4);
    float4 s2a = *(const float4*)(g_S2 + c0);
    float4 s2b = *(const float4*)(g_S2 + c0 + 4);
    float s1[8] = {s1a.x, s1a.y, s1a.z, s1a.w, s1b.x, s1b.y, s1b.z, s1b.w};
    float s2[8] = {s2a.x, s2a.y, s2a.z, s2a.w, s2b.x, s2b.y, s2b.z, s2b.w};
    #pragma unroll
    for (int p = 0; p < 4; p++) {
        int r0 = bm0 + rowb + 2 * p;
        float mu0 = g_mu[r0 * M + mi], rs0 = g_rsd[r0 * M + mi];
        float mu1 = g_mu[(r0 + 1) * M + mi], rs1 = g_rsd[(r0 + 1) * M + mi];
        float o0[8], o1[8];
        #pragma unroll
        for (int j = 0; j < 8; j++) {
            float2 v = unpack2(acc[p][j]);
            o0[j] = (v.x - mu0 * s1[j]) * rs0 + s2[j];
            o1[j] = (v.y - mu1 * s1[j]) * rs1 + s2[j];
        }
        float* po0 = g_priors + (size_t)r0 * NCOL + c0;
        float* po1 = po0 + NCOL;
        *(float4*)(po0)     = make_float4(o0[0], o0[1], o0[2], o0[3]);
        *(float4*)(po0 + 4) = make_float4(o0[4], o0[5], o0[6], o0[7]);
        *(float4*)(po1)     = make_float4(o1[0], o1[1], o1[2], o1[3]);
        *(float4*)(po1 + 4) = make_float4(o1[4], o1[5], o1[6], o1[7]);
    }
}

// ---------------- K4: fused routing, warp-per-capsule -------------
__global__ __launch_bounds__(256) void k_route(const float* __restrict__ leaves,
                                               const float* __restrict__ thr,
                                               const float* __restrict__ cg,
                                               const float* __restrict__ cb,
                                               const float* __restrict__ y,
                                               float* __restrict__ outp) {
    __shared__ __align__(16) float pri[NCOL];
    __shared__ float thrsh[M * NCAP];
    __shared__ float probw[8][34];
    __shared__ float hid[NCAP * T];
    __shared__ float snorm[NCAP];
    __shared__ float ysh[NC];
    __shared__ float cgs[T], cbs[T];
    int b = blockIdx.x, tid = threadIdx.x;
    int lane = tid & 31, w = tid >> 5;
    const float4* src = (const float4*)(g_priors + (size_t)b * NCOL);
    for (int i = tid; i < NCOL / 4; i += 256) ((float4*)pri)[i] = src[i];
    for (int i = tid; i < M * NCAP; i += 256) thrsh[i] = thr[i];
    if (tid < NC) ysh[tid] = y[b * NC + tid];
    if (tid < T) { cgs[tid] = cg[tid]; cbs[tid] = cb[tid]; }
    float lf[T];
    float ss = 0.f;
    #pragma unroll
    for (int t = 0; t < T; t++) { lf[t] = leaves[lane * T + t]; ss += lf[t] * lf[t]; }
    float invn = 1.f / fmaxf(sqrtf(ss), 1e-12f);
    ull lh8[8];
    #pragma unroll
    for (int i = 0; i < 8; i++) lh8[i] = pack2(lf[2 * i] * invn, lf[2 * i + 1] * invn);
    __syncthreads();

    #pragma unroll
    for (int rep = 0; rep < 2; rep++) {
        int n = w * 2 + rep;
        float v[M];
        #pragma unroll
        for (int m = 0; m < M; m++) {
            const ull* pp = (const ull*)&pri[m * 256 + n * T];
            ull a = 0ULL;
            #pragma unroll
            for (int i = 0; i < 8; i++) ffma2(a, pp[i], lh8[i]);
            float2 s2v = unpack2(a);
            float d = s2v.x + s2v.y;
            v[m] = 1.f / (1.f + __expf(-d));
        }
        float vb = 0.f;
        #pragma unroll
        for (int m = 0; m < M; m++) vb += v[m];
        vb *= (1.f / 33.f);
        float wgt_own = 0.f, wgt32 = 0.f;
        #pragma unroll
        for (int m = 0; m < M; m++) {
            float d = v[m] - vb;
            d *= d;
            #pragma unroll
            for (int o = 16; o; o >>= 1) d += __shfl_xor_sync(0xffffffffu, d, o);
            float dis = d * (1.f / 32.f);
            float th = thrsh[m * NCAP + n];
            float wv = th * th - dis;
            wv = wv > 0.f ? wv : 0.f;
            if (m == lane) wgt_own = wv;
            if (m == 32) wgt32 = wv;
        }
        float mx = fmaxf(wgt_own, wgt32);
        #pragma unroll
        for (int o = 16; o; o >>= 1) mx = fmaxf(mx, __shfl_xor_sync(0xffffffffu, mx, o));
        float e = __expf(wgt_own - mx);
        float e32 = __expf(wgt32 - mx);
        float sm = e;
        #pragma unroll
        for (int o = 16; o; o >>= 1) sm += __shfl_xor_sync(0xffffffffu, sm, o);
        float inv = 1.f / (sm + e32);
        probw[w][lane] = e * inv;
        if (lane == 0) probw[w][32] = e32 * inv;
        __syncwarp();
        if (lane < T) {
            float h = 0.f;
            #pragma unroll
            for (int m = 0; m < M; m++) h += probw[w][m] * pri[m * 256 + n * T + lane];
            float s = h;
            #pragma unroll
            for (int o = 8; o; o >>= 1) s += __shfl_xor_sync(0xffffu, s, o);
            float mean = s * (1.f / 16.f);
            float dv = h - mean;
            float vs = dv * dv;
            #pragma unroll
            for (int o = 8; o; o >>= 1) vs += __shfl_xor_sync(0xffffu, vs, o);
            float rs = rsqrtf(vs * (1.f / 16.f) + EPS);
            float hl = dv * rs * cgs[lane] + cbs[lane];
            hid[n * T + lane] = hl;
            float q = hl * hl;
            #pragma unroll
            for (int o = 8; o; o >>= 1) q += __shfl_xor_sync(0xffffu, q, o);
            if (lane == 0) snorm[n] = sqrtf(q);
        }
        __syncwarp();
    }
    __syncthreads();
    if (tid < NC) {
        float s = snorm[tid * 4 + 0] + snorm[tid * 4 + 1] +
                  snorm[tid * 4 + 2] + snorm[tid * 4 + 3];
        outp[b * NC + tid] = s;
    }
    if (tid < DIN1) {
        int s = tid >> 4, t = tid & 15;
        float a = 0.f;
        #pragma unroll
        for (int c = 0; c < NC; c++) a += hid[(s * 4 + c) * T + t] * ysh[c];
        g_hsel[b * DIN1 + tid] = a;
    }
}

// ---------------- K5: entmax of decoder masks ---------------------
__global__ void k_entmax_small(const float* __restrict__ m1, const float* __restrict__ m2) {
    __shared__ float xo[128], srt[128], cs[128], cs2[128], tau[128], red[128];
    int bi = blockIdx.x, tid = threadIdx.x;
    int which = bi / 3, p = bi % 3;
    int d = which ? DIN2 : DIN1;
    const float* s = which ? (m2 + p * DIN2) : (m1 + p * DIN1);
    float* dst = which ? (g_mask2 + p * DIN2) : (g_mask1 + p * DIN1);
    xo[tid] = (tid < d) ? s[tid] : -FLT_MAX;
    __syncthreads();
    float ts = entmax_tau_block<128>(xo, srt, cs, cs2, tau, red, d);
    if (tid < d) {
        float r = fmaxf(xo[tid] - ts, 0.f);
        dst[tid] = r * r;
    }
}

// ---------------- K7: h1 = hsel @ (mask1*W1)^T + b1 ---------------
__global__ void k_h1(const float* __restrict__ b1, const float* __restrict__ w1) {
    __shared__ float xs[DIN1];
    __shared__ float msk[3 * DIN1];
    int b = blockIdx.x, tid = threadIdx.x;   // 96 threads
    if (tid < DIN1) xs[tid] = g_hsel[b * DIN1 + tid];
    for (int i = tid; i < 3 * DIN1; i += 96) msk[i] = g_mask1[i];
    __syncthreads();
    float a = b1[tid];
    const float* wr = w1 + tid * DIN1;
    const float* mr = msk + (tid >> 5) * DIN1;
    #pragma unroll 4
    for (int d = 0; d < DIN1; d++) a += wr[d] * mr[d] * xs[d];
    g_h1[b * 96 + tid] = a;
}

// ---------------- GhostBN stats (device-side global refs) ---------
__global__ void k_gbn_stats1() {
    int g = blockIdx.x, j = threadIdx.x;          // F = 96
    const float* p = g_h1 + (size_t)g * VBS * 96 + j;
    float s = 0.f, s2 = 0.f;
    for (int r = 0; r < VBS; r++) {
        float v = p[r * 96];
        s += v; s2 += v * v;
    }
    float mean = s * (1.f / (float)VBS);
    float var = s2 * (1.f / (float)VBS) - mean * mean;
    g_st1[g * 96 + j] = mean;
    g_st1[NG * 96 + g * 96 + j] = rsqrtf(var + EPS);
}

__global__ void k_gbn_stats2() {
    int g = blockIdx.x, j = threadIdx.x;          // F = 192
    const float* p = g_g2 + (size_t)g * VBS * 192 + j;
    float s = 0.f, s2 = 0.f;
    for (int r = 0; r < VBS; r++) {
        float v = p[r * 192];
        s += v; s2 += v * v;
    }
    float mean = s * (1.f / (float)VBS);
    float var = s2 * (1.f / (float)VBS) - mean * mean;
    g_st2[g * 192 + j] = mean;
    g_st2[NG * 192 + g * 192 + j] = rsqrtf(var + EPS);
}

// ---------------- K9: apply GBN1 + GLU + build h2 -----------------
__global__ void k_apply1(const float* __restrict__ bg, const float* __restrict__ bb) {
    __shared__ float hh[96];
    int b = blockIdx.x, tid = threadIdx.x;
    int g = b >> 8;
    float v = g_h1[b * 96 + tid];
    float mean = g_st1[g * 96 + tid];
    float rs = g_st1[NG * 96 + g * 96 + tid];
    hh[tid] = (v - mean) * rs * bg[tid] + bb[tid];
    __syncthreads();
    if (tid < 16) {
        float s = 0.f;
        #pragma unroll
        for (int p = 0; p < 3; p++) {
            float gte = 1.f / (1.f + __expf(-hh[p * 32 + tid]));
            float pr = gte * hh[p * 32 + 16 + tid];
            s += pr > 0.f ? pr : 0.f;
        }
        g_h2[b * DIN2 + DIN1 + tid] = s;
    }
    if (tid < DIN1) g_h2[b * DIN2 + tid] = g_hsel[b * DIN1 + tid];
}

// ---------------- K10: g2 = h2 @ (mask2*W2)^T + b2 ----------------
__global__ void k_h2(const float* __restrict__ b2, const float* __restrict__ w2) {
    __shared__ float xs[DIN2];
    __shared__ float msk[3 * DIN2];
    int b = blockIdx.x, tid = threadIdx.x;   // 192 threads
    if (tid < DIN2) xs[tid] = g_h2[b * DIN2 + tid];
    for (int i = tid; i < 3 * DIN2; i += 192) msk[i] = g_mask2[i];
    __syncthreads();
    float a = b2[tid];
    const float* wr = w2 + tid * DIN2;
    const float* mr = msk + (tid / 64) * DIN2;
    #pragma unroll 4
    for (int d = 0; d < DIN2; d++) a += wr[d] * mr[d] * xs[d];
    g_g2[b * 192 + tid] = a;
}

// ---------------- K12: apply GBN2 + GLU + final linear ------------
__global__ void k_apply2(const float* __restrict__ bg, const float* __restrict__ bb,
                         const float* __restrict__ dw, const float* __restrict__ db,
                         float* __restrict__ rec) {
    __shared__ float hh[192];
    __shared__ float o2[32];
    int b = blockIdx.x, tid = threadIdx.x;
    int g = b >> 8;
    float v = g_g2[b * 192 + tid];
    float mean = g_st2[g * 192 + tid];
    float rs = g_st2[NG * 192 + g * 192 + tid];
    hh[tid] = (v - mean) * rs * bg[tid] + bb[tid];
    __syncthreads();
    if (tid < 32) {
        float s = 0.f;
        #pragma unroll
        for (int p = 0; p < 3; p++) {
            float gte = 1.f / (1.f + __expf(-hh[p * 64 + tid]));
            float pr = gte * hh[p * 64 + 32 + tid];
            s += pr > 0.f ? pr : 0.f;
        }
        o2[tid] = s;
    }
    __syncthreads();
    if (tid < INDIM) {
        float a = db[tid];
        const float* wr = dw + tid * 32;
        #pragma unroll
        for (int o = 0; o < 32; o++) a += wr[o] * o2[o];
        rec[b * INDIM + tid] = a;
    }
}

// ------------------------- launch ---------------------------------
extern "C" void kernel_launch(void* const* d_in, const int* in_sizes, int n_in,
                              void* d_out, int out_size) {
    const float* x       = (const float*)d_in[0];
    const float* y       = (const float*)d_in[1];
    const float* init_w  = (const float*)d_in[2];
    const float* init_b  = (const float*)d_in[3];
    const float* eln_g   = (const float*)d_in[4];
    const float* eln_b   = (const float*)d_in[5];
    const float* prim_fc = (const float*)d_in[6];
    const float* route_w = (const float*)d_in[7];
    const float* thread_ = (const float*)d_in[8];
    const float* leaves  = (const float*)d_in[9];
    const float* cln_g   = (const float*)d_in[10];
    const float* cln_b   = (const float*)d_in[11];
    const float* m1_w    = (const float*)d_in[12];
    const float* fc1_w   = (const float*)d_in[13];
    const float* fc1_b   = (const float*)d_in[14];
    const float* bn1_g   = (const float*)d_in[15];
    const float* bn1_b   = (const float*)d_in[16];
    const float* m2_w    = (const float*)d_in[17];
    const float* fc2_w   = (const float*)d_in[18];
    const float* fc2_b   = (const float*)d_in[19];
    const float* bn2_g   = (const float*)d_in[20];
    const float* bn2_b   = (const float*)d_in[21];
    const float* dec_w   = (const float*)d_in[22];
    const float* dec_b   = (const float*)d_in[23];
    float* out = (float*)d_out;           // [B*NC pred][B*INDIM rec]

    k_prep<<<B, 192>>>(x, init_w, init_b, prim_fc);
    k_entmax_route<<<NCOL, 256>>>(route_w, eln_g, eln_b, prim_fc);
    k_entmax_small<<<6, 128>>>(m1_w, m2_w);
    k_gemm<<<dim3(NCOL / 128, B / 128), 256>>>();
    k_route<<<B, 256>>>(leaves, thread_, cln_g, cln_b, y, out);
    k_h1<<<B, 96>>>(fc1_b, fc1_w);
    k_gbn_stats1<<<NG, 96>>>();
    k_apply1<<<B, 96>>>(bn1_g, bn1_b);
    k_h2<<<B, 192>>>(fc2_b, fc2_w);
    k_gbn_stats2<<<NG, 192>>>();
    k_apply2<<<B, 192>>>(bn2_g, bn2_b, dec_w, dec_b, out + B * NC);
}